// round 13
// baseline (speedup 1.0000x reference)
#include <cuda_runtime.h>
#include <cstdint>

// FWHT over contiguous groups of 128 fp32 elements.
// 8 lanes per group; each thread holds 16 CONTIGUOUS elements per tile slot
// (LDG.256 x2), and TWO tile slots -> 4 front-batched 32B loads = 128 B
// in flight per thread before any compute. Longer pure-read / pure-write
// bursts per warp = fewer DRAM read<->write turnarounds.
// Stages h=1,2,4,8 intra-thread; h=16,32,64 via shfl.xor deltas 1,2,4.

__device__ __forceinline__ void ldg256_keep(const float* p, float* r) {
    asm volatile(
        "ld.global.nc.L2::evict_last.v8.f32 {%0,%1,%2,%3,%4,%5,%6,%7}, [%8];"
        : "=f"(r[0]), "=f"(r[1]), "=f"(r[2]), "=f"(r[3]),
          "=f"(r[4]), "=f"(r[5]), "=f"(r[6]), "=f"(r[7])
        : "l"(p));
}

__device__ __forceinline__ void stg256_stream(float* p, const float* r) {
    asm volatile(
        "st.global.cs.v8.f32 [%0], {%1,%2,%3,%4,%5,%6,%7,%8};"
        :: "l"(p),
           "f"(r[0]), "f"(r[1]), "f"(r[2]), "f"(r[3]),
           "f"(r[4]), "f"(r[5]), "f"(r[6]), "f"(r[7])
        : "memory");
}

__device__ __forceinline__ void fwht16_local(float* e) {
    float t;
    #pragma unroll
    for (int h = 1; h <= 8; h <<= 1) {
        #pragma unroll
        for (int i = 0; i < 16; ++i) {
            if ((i & h) == 0) {
                t = e[i];
                e[i]     = t + e[i + h];
                e[i + h] = t - e[i + h];
            }
        }
    }
}

__global__ void __launch_bounds__(256) fwht128_kernel(
    const float* __restrict__ in, float* __restrict__ out)
{
    const unsigned int lane = threadIdx.x & 31u;
    // Each block owns 8192 contiguous floats = two 4096-float tiles.
    // Thread i: elements [i*16, i*16+16) of tile 0 and of tile 1.
    const unsigned int base0 = blockIdx.x * 8192u + threadIdx.x * 16u;
    const unsigned int base1 = base0 + 4096u;

    float e0[16], e1[16];
    // Front-batched: 4 x 32B loads in flight per thread.
    ldg256_keep(in + base0,      e0);
    ldg256_keep(in + base0 + 8u, e0 + 8);
    ldg256_keep(in + base1,      e1);
    ldg256_keep(in + base1 + 8u, e1 + 8);

    // Intra-thread stages h=1,2,4,8.
    fwht16_local(e0);
    fwht16_local(e1);

    // Cross-lane stages h=16,32,64 -> shfl.xor deltas 1,2,4 (within 8 lanes).
    #pragma unroll
    for (int d = 1; d <= 4; d <<= 1) {
        bool up = (lane & (unsigned)d) != 0u;
        #pragma unroll
        for (int k = 0; k < 16; ++k) {
            float q0 = __shfl_xor_sync(0xffffffffu, e0[k], d);
            float q1 = __shfl_xor_sync(0xffffffffu, e1[k], d);
            e0[k] = up ? (q0 - e0[k]) : (e0[k] + q0);
            e1[k] = up ? (q1 - e1[k]) : (e1[k] + q1);
        }
    }

    const float S = 0.08838834764831845f;  // 1/sqrt(128)
    float r[8];
    #pragma unroll
    for (int k = 0; k < 8; ++k) r[k] = e0[k] * S;
    stg256_stream(out + base0, r);
    #pragma unroll
    for (int k = 0; k < 8; ++k) r[k] = e0[k + 8] * S;
    stg256_stream(out + base0 + 8u, r);
    #pragma unroll
    for (int k = 0; k < 8; ++k) r[k] = e1[k] * S;
    stg256_stream(out + base1, r);
    #pragma unroll
    for (int k = 0; k < 8; ++k) r[k] = e1[k + 8] * S;
    stg256_stream(out + base1 + 8u, r);
}

extern "C" void kernel_launch(void* const* d_in, const int* in_sizes, int n_in,
                              void* d_out, int out_size)
{
    const float* x = (const float*)d_in[0];
    float* y = (float*)d_out;
    unsigned int n = (unsigned int)in_sizes[0];   // 67108864
    unsigned int grid = n / 8192u;                // = 8192, exact
    fwht128_kernel<<<grid, 256>>>(x, y);
}

// round 14
// speedup vs baseline: 1.0055x; 1.0055x over previous
#include <cuda_runtime.h>
#include <cstdint>

// FWHT over contiguous groups of 128 fp32 elements — FINAL (best: 81.89 us).
//
// Layout: 8 lanes per group; each thread holds 16 CONTIGUOUS elements
// (2x 256-bit LDG). Stages h=1,2,4,8 are intra-thread register butterflies;
// stages h=16,32,64 are shfl.xor with deltas 1,2,4 (3 shuffles/element).
// 32 regs, no smem, no barriers, exact-cover grid.
//
// Roofline verdict (13 rounds, 12 configs): pinned at the sustained 1:1
// read:write HBM3e ceiling, ~6.3-6.4 TB/s (~80% of 8 TB/s spec), traffic at
// the 512 MB/replay algorithmic minimum. MLP, occupancy, shuffle count,
// access width, persistence, block size, L2 hints, and per-thread burst
// length were each individually falsified as levers.

__device__ __forceinline__ void ldg256_keep(const float* p, float* r) {
    asm volatile(
        "ld.global.nc.L2::evict_last.v8.f32 {%0,%1,%2,%3,%4,%5,%6,%7}, [%8];"
        : "=f"(r[0]), "=f"(r[1]), "=f"(r[2]), "=f"(r[3]),
          "=f"(r[4]), "=f"(r[5]), "=f"(r[6]), "=f"(r[7])
        : "l"(p));
}

__device__ __forceinline__ void stg256_stream(float* p, const float* r) {
    asm volatile(
        "st.global.cs.v8.f32 [%0], {%1,%2,%3,%4,%5,%6,%7,%8};"
        :: "l"(p),
           "f"(r[0]), "f"(r[1]), "f"(r[2]), "f"(r[3]),
           "f"(r[4]), "f"(r[5]), "f"(r[6]), "f"(r[7])
        : "memory");
}

__global__ void __launch_bounds__(256) fwht128_kernel(
    const float* __restrict__ in, float* __restrict__ out)
{
    const unsigned int lane = threadIdx.x & 31u;
    // Each thread: 16 contiguous floats. Each warp: 512 floats = 4 groups.
    const unsigned int base = (blockIdx.x * 256u + threadIdx.x) * 16u;

    float e[16];
    ldg256_keep(in + base, e);
    ldg256_keep(in + base + 8u, e + 8);

    // Intra-thread stages h=1,2,4,8 (FWHT-16 on contiguous elements).
    float t;
    #pragma unroll
    for (int h = 1; h <= 8; h <<= 1) {
        #pragma unroll
        for (int i = 0; i < 16; ++i) {
            if ((i & h) == 0) {
                t = e[i];
                e[i]     = t + e[i + h];
                e[i + h] = t - e[i + h];
            }
        }
    }

    // Cross-lane stages h=16,32,64 -> shfl.xor deltas 1,2,4 (within 8 lanes).
    #pragma unroll
    for (int d = 1; d <= 4; d <<= 1) {
        bool up = (lane & (unsigned)d) != 0u;
        #pragma unroll
        for (int k = 0; k < 16; ++k) {
            float q = __shfl_xor_sync(0xffffffffu, e[k], d);
            e[k] = up ? (q - e[k]) : (e[k] + q);
        }
    }

    const float S = 0.08838834764831845f;  // 1/sqrt(128)
    float r[8];
    #pragma unroll
    for (int k = 0; k < 8; ++k) r[k] = e[k] * S;
    stg256_stream(out + base, r);
    #pragma unroll
    for (int k = 0; k < 8; ++k) r[k] = e[k + 8] * S;
    stg256_stream(out + base + 8u, r);
}

extern "C" void kernel_launch(void* const* d_in, const int* in_sizes, int n_in,
                              void* d_out, int out_size)
{
    const float* x = (const float*)d_in[0];
    float* y = (float*)d_out;
    unsigned int n = (unsigned int)in_sizes[0];   // 67108864
    unsigned int grid = n / (256u * 16u);         // = 16384, exact
    fwht128_kernel<<<grid, 256>>>(x, y);
}